// round 10
// baseline (speedup 1.0000x reference)
#include <cuda_runtime.h>
#include <cuda_fp16.h>
#include <math.h>
#include <cstdint>

#define B 8
#define C 64
#define H 256
#define W 256
#define HW 65536
#define P 16
#define OC 64
#define NBINS 256
#define OUTC 112   // OC + (C-P)

// Device scratch
__device__ float g_act[B * C];
__device__ int   g_top[B * P];
__device__ int   g_unsel[B * (C - P)];
__device__ int   g_cnt[B];     // channels finished per batch
__device__ int   g_flag[B];    // selection ready per batch

__device__ __forceinline__ uint32_t smem_u32(const void* p) {
    uint32_t a;
    asm("{ .reg .u64 t; cvta.to.shared.u64 t, %1; cvt.u32.u64 %0, t; }"
        : "=r"(a) : "l"(p));
    return a;
}
__device__ __forceinline__ void cp_async4(uint32_t saddr, const float* g) {
    asm volatile("cp.async.ca.shared.global [%0], [%1], 4;"
                 :: "r"(saddr), "l"(g) : "memory");
}

// ===========================================================================
// init: reset per-launch coordination state (graph-deterministic)
// ===========================================================================
__global__ void k_init() {
    if (threadIdx.x < B) { g_cnt[threadIdx.x] = 0; g_flag[threadIdx.x] = 0; }
}

// ===========================================================================
// Fused persistent kernel: stats -> (inline per-batch topk) -> conv + copy.
// 296 CTAs, 2/SM, all resident => spin-waits are deadlock-free.
// ===========================================================================
#define APITCH 12
#define RPITCH 20
#define AROW   132
#define NSLOT  520                           // 130 x 4 active slots
#define RAW_WORDS (4 * AROW * RPITCH)        // 10560
#define PKD_WORDS (4 * AROW * APITCH)        // 6336
#define BPITCH 72
#define SW_WORDS  (72 * BPITCH)              // 5184
#define CONV_SMEM ((RAW_WORDS + PKD_WORDS + SW_WORDS) * 4)  // 88320 bytes
#define NTILES (B * (H / 2) * (W / 128))     // 2048
#define NCTA   296
#define COPY_F4_PER_TILE 3072                // 6291456 / 2048

__global__ void __launch_bounds__(256, 2)
k_fused(const float* __restrict__ x, const float* __restrict__ wgt,
        const float* __restrict__ bias, float* __restrict__ out) {
    extern __shared__ uint32_t smem_w[];
    uint32_t* rawW = smem_w;                       // fp32 gather staging
    uint32_t* sIn  = smem_w + RAW_WORDS;           // packed half2
    uint32_t* sW   = smem_w + RAW_WORDS + PKD_WORDS;
    __shared__ float sB[OC];
    __shared__ float s_mn, s_den;
    __shared__ int   s_ready;

    int tid  = threadIdx.x;
    int wid  = tid >> 5;
    int lane = tid & 31;
    int bid  = blockIdx.x;
    uint32_t rawA = smem_u32(rawW);

    // ---- one-time: weights (half2 [72][BPITCH]) + bias ----
    for (int i = tid; i < 72 * OC; i += 256) {
        int oc  = i & 63;
        int row = i >> 6;
        int tap = row >> 3;
        int w2  = row & 7;
        float f0 = wgt[oc * (P * 9) + (2 * w2)     * 9 + tap];
        float f1 = wgt[oc * (P * 9) + (2 * w2 + 1) * 9 + tap];
        __half2 hp = __floats2half2_rn(f0, f1);
        sW[row * BPITCH + oc] = *reinterpret_cast<uint32_t*>(&hp);
    }
    if (tid < OC) sB[tid] = bias[tid];

    // ======================= PHASE 1: stats =======================
    // smem scratch overlaid on raw region (conv untouched regions safe)
    float* smn  = (float*)rawW;          // [256]
    float* smx  = smn + 256;             // [256]
    float* sred = smx + 256;             // [256]
    int*   shh  = (int*)(sred + 256);    // [8][256]

    for (int bc = bid; bc < B * C; bc += NCTA) {
        const float4* p = (const float4*)(x + (size_t)bc * HW);

        float mn = 3.402823466e+38f, mx = -3.402823466e+38f;
#pragma unroll 8
        for (int i = tid; i < HW / 4; i += 256) {
            float4 v = p[i];
            mn = fminf(mn, fminf(fminf(v.x, v.y), fminf(v.z, v.w)));
            mx = fmaxf(mx, fmaxf(fmaxf(v.x, v.y), fmaxf(v.z, v.w)));
        }
        smn[tid] = mn; smx[tid] = mx;
#pragma unroll
        for (int w = 0; w < 8; w++) shh[w * 256 + tid] = 0;
        __syncthreads();
        for (int s = 128; s > 0; s >>= 1) {
            if (tid < s) {
                smn[tid] = fminf(smn[tid], smn[tid + s]);
                smx[tid] = fmaxf(smx[tid], smx[tid + s]);
            }
            __syncthreads();
        }
        if (tid == 0) { s_mn = smn[0]; s_den = smx[0] - smn[0] + 1e-8f; }
        __syncthreads();

        float bmn  = s_mn, bden = s_den;
        float binv = __frcp_rn(bden);
        int* myh = shh + wid * 256;
#pragma unroll 4
        for (int i = tid; i < HW / 4; i += 256) {
            float4 v = p[i];
            float vs[4] = {v.x, v.y, v.z, v.w};
#pragma unroll
            for (int k = 0; k < 4; k++) {
                float d  = vs[k] - bmn;
                float q0 = d * binv;                 // Markstein: matches div.rn
                float r  = fmaf(-bden, q0, d);
                float xn = fmaf(r, binv, q0);
                int bn = (int)(xn * 256.0f);
                bn = bn < 0 ? 0 : (bn > 255 ? 255 : bn);
                atomicAdd(&myh[bn], 1);
            }
        }
        __syncthreads();

        int cnt = 0;
#pragma unroll
        for (int w = 0; w < 8; w++) cnt += shh[w * 256 + tid];
        float hv = (float)cnt + 1e-8f;
        sred[tid] = hv;
        __syncthreads();
        for (int s = 128; s > 0; s >>= 1) {
            if (tid < s) sred[tid] += sred[tid + s];
            __syncthreads();
        }
        float total = sred[0];
        __syncthreads();
        float prob = __fdiv_rn(hv, total);
        sred[tid] = prob * logf(prob + 1e-8f);
        __syncthreads();
        for (int s = 128; s > 0; s >>= 1) {
            if (tid < s) sred[tid] += sred[tid + s];
            __syncthreads();
        }

        if (tid == 0) {
            g_act[bc] = -sred[0];
            __threadfence();
            int b = bc >> 6;
            int done = atomicAdd(&g_cnt[b], 1) + 1;
            if (done == C) {
                // last channel of batch b: run topk inline (stable tie-break)
                __threadfence();
                float a[C];
                bool used[C];
                for (int c = 0; c < C; c++) {
                    a[c] = __ldcg(&g_act[b * C + c]);
                    used[c] = false;
                }
                for (int pp = 0; pp < P; pp++) {
                    float best = -3.402823466e+38f;
                    int bi = -1;
                    for (int c = 0; c < C; c++)
                        if (!used[c] && a[c] > best) { best = a[c]; bi = c; }
                    used[bi] = true;
                    g_top[b * P + pp] = bi;
                }
                int k = 0;
                for (int c = 0; c < C; c++)
                    if (!used[c]) g_unsel[b * (C - P) + (k++)] = c;
                __threadfence();
                atomicExch(&g_flag[b], 1);
            }
        }
        __syncthreads();   // smem scratch reuse
    }

    // ======================= PHASE 2: conv + copy =======================
    int gp = lane >> 2;
    int kc = lane & 3;
    int wrow = wid >> 2;
    int wcol = wid & 3;
    int pbase = wcol * 32 + gp;

    auto stage_issue = [&](int tile) {
        int tb  = tile >> 8;
        int rem = tile & 255;
        int h0  = (rem >> 1) * 2;
        int w0  = (rem & 1) * 128;
        int ch[16];
#pragma unroll
        for (int c = 0; c < 16; c++) ch[c] = __ldcg(&g_top[tb * P + c]);
        const float* xb = x + ((size_t)tb * C) * HW;
        for (int i = tid; i < NSLOT; i += 256) {
            int pr = i / 130;
            int pp = i - pr * 130;
            int gw = w0 - 1 + pp;
            int gh = h0 - 1 + pr;
            uint32_t dst = rawA + (uint32_t)((pr * AROW + pp) * RPITCH) * 4u;
            if (((unsigned)gw < (unsigned)W) && ((unsigned)gh < (unsigned)H)) {
                const float* src = xb + gh * W + gw;
#pragma unroll
                for (int c = 0; c < 16; c++)
                    cp_async4(dst + c * 4u, src + (size_t)ch[c] * HW);
            } else {
                uint4 z = make_uint4(0u, 0u, 0u, 0u);
#pragma unroll
                for (int q = 0; q < 4; q++)
                    *(uint4*)((char*)rawW + (dst - rawA) + q * 16) = z;
            }
        }
        asm volatile("cp.async.commit_group;" ::: "memory");
    };

    auto wait_flag = [&](int b) {
        if (tid == 0) {
            while (atomicAdd(&g_flag[b], 0) == 0) __nanosleep(64);
        }
        __syncthreads();
    };

    bool pref = false;
    for (int t = bid; t < NTILES; t += NCTA) {
        if (!pref) {
            wait_flag(t >> 8);
            stage_issue(t);
        }
        asm volatile("cp.async.wait_group 0;" ::: "memory");
        __syncthreads();

        // convert raw fp32 -> packed half2
        for (int i = tid; i < NSLOT; i += 256) {
            int pr = i / 130;
            int pp = i - pr * 130;
            const float4* rs = (const float4*)(rawW + (pr * AROW + pp) * RPITCH);
            float4 r0 = rs[0], r1 = rs[1], r2 = rs[2], r3 = rs[3];
            __half2 h0 = __floats2half2_rn(r0.x, r0.y);
            __half2 h1 = __floats2half2_rn(r0.z, r0.w);
            __half2 h2 = __floats2half2_rn(r1.x, r1.y);
            __half2 h3 = __floats2half2_rn(r1.z, r1.w);
            __half2 h4 = __floats2half2_rn(r2.x, r2.y);
            __half2 h5 = __floats2half2_rn(r2.z, r2.w);
            __half2 h6 = __floats2half2_rn(r3.x, r3.y);
            __half2 h7 = __floats2half2_rn(r3.z, r3.w);
            uint32_t* dst = sIn + (pr * AROW + pp) * APITCH;
            *(uint4*)(dst) = make_uint4(
                *reinterpret_cast<uint32_t*>(&h0), *reinterpret_cast<uint32_t*>(&h1),
                *reinterpret_cast<uint32_t*>(&h2), *reinterpret_cast<uint32_t*>(&h3));
            *(uint4*)(dst + 4) = make_uint4(
                *reinterpret_cast<uint32_t*>(&h4), *reinterpret_cast<uint32_t*>(&h5),
                *reinterpret_cast<uint32_t*>(&h6), *reinterpret_cast<uint32_t*>(&h7));
        }
        __syncthreads();   // packed ready; raw free

        // prefetch next tile if its batch is already released
        int tn = t + NCTA;
        pref = false;
        if (tn < NTILES) {
            if (tid == 0) s_ready = atomicAdd(&g_flag[tn >> 8], 0);
            __syncthreads();
            if (s_ready) { stage_issue(tn); pref = true; }
        }

        // mainloop
        int b   = t >> 8;
        int rem = t & 255;
        int h0  = (rem >> 1) * 2;
        int w0  = (rem & 1) * 128;

        float acc[2][8][4];
#pragma unroll
        for (int m = 0; m < 2; m++)
#pragma unroll
            for (int j = 0; j < 8; j++)
#pragma unroll
                for (int r = 0; r < 4; r++) acc[m][j][r] = 0.f;

#pragma unroll
        for (int tap = 0; tap < 9; tap++) {
            int arow0 = (wrow + tap / 3) * AROW + (tap % 3);
            uint32_t a[2][4];
#pragma unroll
            for (int m = 0; m < 2; m++) {
                int base0 = (arow0 + pbase + m * 16) * APITCH;
                a[m][0] = sIn[base0 + kc];
                a[m][1] = sIn[base0 + 8 * APITCH + kc];
                a[m][2] = sIn[base0 + kc + 4];
                a[m][3] = sIn[base0 + 8 * APITCH + kc + 4];
            }
            const uint32_t* b0row = sW + (tap * 8 + kc)     * BPITCH + gp;
            const uint32_t* b1row = sW + (tap * 8 + kc + 4) * BPITCH + gp;
#pragma unroll
            for (int j = 0; j < 8; j++) {
                uint32_t b0 = b0row[j * 8];
                uint32_t b1 = b1row[j * 8];
#pragma unroll
                for (int m = 0; m < 2; m++) {
                    asm volatile(
                        "mma.sync.aligned.m16n8k16.row.col.f32.f16.f16.f32 "
                        "{%0,%1,%2,%3}, {%4,%5,%6,%7}, {%8,%9}, {%0,%1,%2,%3};"
                        : "+f"(acc[m][j][0]), "+f"(acc[m][j][1]),
                          "+f"(acc[m][j][2]), "+f"(acc[m][j][3])
                        : "r"(a[m][0]), "r"(a[m][1]), "r"(a[m][2]), "r"(a[m][3]),
                          "r"(b0), "r"(b1));
                }
            }
        }

        // direct stores (8-px runs fill 32B sectors)
        size_t obase = ((size_t)b * OUTC) * HW + (size_t)(h0 + wrow) * W + w0;
#pragma unroll
        for (int m = 0; m < 2; m++) {
            int px = pbase + m * 16;
#pragma unroll
            for (int j = 0; j < 8; j++) {
                int oc0 = j * 8 + 2 * kc;
                float bb0 = sB[oc0], bb1 = sB[oc0 + 1];
                float* o0 = out + obase + (size_t)oc0 * HW + px;
                float* o1 = o0 + HW;
                o0[0] = acc[m][j][0] + bb0;
                o1[0] = acc[m][j][1] + bb1;
                o0[8] = acc[m][j][2] + bb0;
                o1[8] = acc[m][j][3] + bb1;
            }
        }

        // fused copy chunk (same batch as this tile -> flag already held)
        {
            size_t base = (size_t)t * COPY_F4_PER_TILE;
#pragma unroll 4
            for (int i = tid; i < COPY_F4_PER_TILE; i += 256) {
                size_t tt = base + i;
                int ch_slot = (int)(tt >> 14);
                int off     = (int)(tt & 16383);
                int cb = ch_slot / (C - P);
                int j  = ch_slot - cb * (C - P);
                int cc = __ldcg(&g_unsel[cb * (C - P) + j]);
                const float4* src = (const float4*)(x + ((size_t)(cb * C + cc)) * HW);
                float4* dst = (float4*)(out + (((size_t)cb * OUTC) + OC + j) * HW);
                dst[off] = src[off];
            }
        }
        __syncthreads();   // done before next convert clobbers sIn
    }
}

// ===========================================================================
extern "C" void kernel_launch(void* const* d_in, const int* in_sizes, int n_in,
                              void* d_out, int out_size) {
    const float* x    = (const float*)d_in[0];
    const float* wgt  = (const float*)d_in[1];
    const float* bias = (const float*)d_in[2];
    float* out = (float*)d_out;

    cudaFuncSetAttribute(k_fused, cudaFuncAttributeMaxDynamicSharedMemorySize,
                         CONV_SMEM);

    k_init<<<1, 32>>>();
    k_fused<<<NCTA, 256, CONV_SMEM>>>(x, wgt, bias, out);
}

// round 11
// speedup vs baseline: 1.2374x; 1.2374x over previous
#include <cuda_runtime.h>
#include <cuda_fp16.h>
#include <math.h>
#include <cstdint>

#define B 8
#define C 64
#define H 256
#define W 256
#define HW 65536
#define P 16
#define OC 64
#define NBINS 256
#define OUTC 112   // OC + (C-P)

// Device scratch
__device__ float g_act[B * C];
__device__ int   g_top[B * P];
__device__ int   g_unsel[B * (C - P)];
__device__ uint4 g_pack[B * HW * 2];   // [b][px][16ch] fp16, 32B per px (16.8MB)

__device__ __forceinline__ uint32_t smem_u32(const void* p) {
    uint32_t a;
    asm("{ .reg .u64 t; cvta.to.shared.u64 t, %1; cvt.u32.u64 %0, t; }"
        : "=r"(a) : "l"(p));
    return a;
}
__device__ __forceinline__ void cp_async16(uint32_t saddr, const void* g) {
    asm volatile("cp.async.cg.shared.global [%0], [%1], 16;"
                 :: "r"(saddr), "l"(g) : "memory");
}

// ===========================================================================
// Kernel 1: fused per-(b,c) min/max + 256-bin histogram + entropy.
// Hoisted reciprocal + Markstein correctly-rounded division (matches div.rn).
// ===========================================================================
__global__ void __launch_bounds__(512)
k_stats(const float* __restrict__ x) {
    __shared__ float smn[512], smx[512];
    __shared__ int   sh[16][NBINS];
    __shared__ float sred[512];
    __shared__ float s_mn, s_den;

    int bc  = blockIdx.x;
    int tid = threadIdx.x;
    int wid = tid >> 5;
    const float4* p = (const float4*)(x + (size_t)bc * HW);

    float mn = 3.402823466e+38f, mx = -3.402823466e+38f;
#pragma unroll 4
    for (int i = tid; i < HW / 4; i += 512) {
        float4 v = p[i];
        mn = fminf(mn, fminf(fminf(v.x, v.y), fminf(v.z, v.w)));
        mx = fmaxf(mx, fmaxf(fmaxf(v.x, v.y), fmaxf(v.z, v.w)));
    }
    smn[tid] = mn; smx[tid] = mx;
    for (int w = 0; w < 16; w++)
        if (tid < NBINS) sh[w][tid] = 0;
    __syncthreads();
    for (int s = 256; s > 0; s >>= 1) {
        if (tid < s) {
            smn[tid] = fminf(smn[tid], smn[tid + s]);
            smx[tid] = fmaxf(smx[tid], smx[tid + s]);
        }
        __syncthreads();
    }
    if (tid == 0) { s_mn = smn[0]; s_den = smx[0] - smn[0] + 1e-8f; }
    __syncthreads();

    float bmn  = s_mn, bden = s_den;
    float binv = __frcp_rn(bden);
    int* myh = sh[wid];
#pragma unroll 2
    for (int i = tid; i < HW / 4; i += 512) {
        float4 v = p[i];
        float vs[4] = {v.x, v.y, v.z, v.w};
#pragma unroll
        for (int k = 0; k < 4; k++) {
            float d  = vs[k] - bmn;
            float q0 = d * binv;
            float r  = fmaf(-bden, q0, d);
            float xn = fmaf(r, binv, q0);
            int bn = (int)(xn * 256.0f);
            bn = bn < 0 ? 0 : (bn > 255 ? 255 : bn);
            atomicAdd(&myh[bn], 1);
        }
    }
    __syncthreads();

    float hv = 0.f;
    if (tid < NBINS) {
        int cnt = 0;
#pragma unroll
        for (int w = 0; w < 16; w++) cnt += sh[w][tid];
        hv = (float)cnt + 1e-8f;
    }
    sred[tid] = hv;
    __syncthreads();
    for (int s = 256; s > 0; s >>= 1) {
        if (tid < s) sred[tid] += sred[tid + s];
        __syncthreads();
    }
    float total = sred[0];
    __syncthreads();

    float term = 0.f;
    if (tid < NBINS) {
        float prob = __fdiv_rn(hv, total);
        term = prob * logf(prob + 1e-8f);
    }
    sred[tid] = term;
    __syncthreads();
    for (int s = 256; s > 0; s >>= 1) {
        if (tid < s) sred[tid] += sred[tid + s];
        __syncthreads();
    }
    if (tid == 0) g_act[bc] = -sred[0];
}

// ===========================================================================
// Kernel 2: top-16 per batch + ascending unselected list.
// ===========================================================================
__global__ void k_topk() {
    __shared__ float sa[C];
    int b = blockIdx.x;
    if (threadIdx.x < C) sa[threadIdx.x] = g_act[b * C + threadIdx.x];
    __syncthreads();
    if (threadIdx.x != 0) return;
    bool used[C];
    for (int c = 0; c < C; c++) used[c] = false;
    for (int p = 0; p < P; p++) {
        float best = -3.402823466e+38f;
        int bi = -1;
        for (int c = 0; c < C; c++)
            if (!used[c] && sa[c] > best) { best = sa[c]; bi = c; }
        used[bi] = true;
        g_top[b * P + p] = bi;
    }
    int k = 0;
    for (int c = 0; c < C; c++)
        if (!used[c]) g_unsel[b * (C - P) + (k++)] = c;
}

// ===========================================================================
// Kernel 3: gather+pack selected channels -> g_pack[b][px][16ch] fp16.
// Coalesced per-channel reads; contiguous 32B writes per pixel.
// ===========================================================================
__global__ void __launch_bounds__(256)
k_gather(const float* __restrict__ x) {
    int blk = blockIdx.x;          // B * 128 blocks, 512 px each
    int b   = blk >> 7;
    int px0 = (blk & 127) << 9;
    int ch[16];
#pragma unroll
    for (int c = 0; c < 16; c++) ch[c] = __ldg(&g_top[b * P + c]);
    const float* xb = x + ((size_t)b * C) * HW;
#pragma unroll
    for (int u = 0; u < 2; u++) {
        int px = px0 + u * 256 + threadIdx.x;
        uint32_t q[8];
#pragma unroll
        for (int c2 = 0; c2 < 8; c2++) {
            float f0 = xb[(size_t)ch[2 * c2]     * HW + px];
            float f1 = xb[(size_t)ch[2 * c2 + 1] * HW + px];
            __half2 hp = __floats2half2_rn(f0, f1);
            q[c2] = *reinterpret_cast<uint32_t*>(&hp);
        }
        uint4* dst = g_pack + ((size_t)b * HW + px) * 2;
        dst[0] = make_uint4(q[0], q[1], q[2], q[3]);
        dst[1] = make_uint4(q[4], q[5], q[6], q[7]);
    }
}

// ===========================================================================
// Kernel 4: persistent fp16 mma conv + fused copy, double-buffered cp.async
// staging from the packed tensor (2 contiguous 16B cp.asyncs per slot).
// Tile = 2 rows x 128 px x 64 oc; K = 144 (9 taps x 16 ch), one K=16
// k-step per tap. Packed pitch 12 words (conflict-free); B pitch 72.
// ===========================================================================
#define APITCH 12
#define AROW   132
#define NSLOT  520                           // 130 x 4 active slots
#define PKD_WORDS (4 * AROW * APITCH)        // 6336 per buffer
#define BPITCH 72
#define SW_WORDS  (72 * BPITCH)              // 5184
#define CONV_SMEM ((2 * PKD_WORDS + SW_WORDS) * 4)   // 71424 bytes
#define NTILES (B * (H / 2) * (W / 128))     // 2048
#define NCTA   296
#define COPY_F4_PER_TILE 3072                // 6291456 / 2048

__global__ void __launch_bounds__(256, 2)
k_conv_mma(const float* __restrict__ x, const float* __restrict__ wgt,
           const float* __restrict__ bias, float* __restrict__ out) {
    extern __shared__ uint32_t smem_w[];
    uint32_t* pkd[2] = { smem_w, smem_w + PKD_WORDS };
    uint32_t* sW = smem_w + 2 * PKD_WORDS;
    __shared__ float sB[OC];

    int tid  = threadIdx.x;
    int wid  = tid >> 5;
    int lane = tid & 31;
    uint32_t pkdA[2] = { smem_u32(pkd[0]), smem_u32(pkd[1]) };

    // one-time: weights (half2 [72][BPITCH]) + bias
    for (int i = tid; i < 72 * OC; i += 256) {
        int oc  = i & 63;
        int row = i >> 6;
        int tap = row >> 3;
        int w2  = row & 7;
        float f0 = wgt[oc * (P * 9) + (2 * w2)     * 9 + tap];
        float f1 = wgt[oc * (P * 9) + (2 * w2 + 1) * 9 + tap];
        __half2 hp = __floats2half2_rn(f0, f1);
        sW[row * BPITCH + oc] = *reinterpret_cast<uint32_t*>(&hp);
    }
    if (tid < OC) sB[tid] = bias[tid];

    int gp = lane >> 2;
    int kc = lane & 3;
    int wrow = wid >> 2;
    int wcol = wid & 3;
    int pbase = wcol * 32 + gp;

    // stage tile into buffer bi: contiguous 32B per slot from g_pack
    auto stage_issue = [&](int tile, int bi) {
        int tb  = tile >> 8;
        int rem = tile & 255;
        int h0  = (rem >> 1) * 2;
        int w0  = (rem & 1) * 128;
        for (int i = tid; i < NSLOT; i += 256) {
            int pr = i / 130;
            int pp = i - pr * 130;
            int gw = w0 - 1 + pp;
            int gh = h0 - 1 + pr;
            uint32_t dst = pkdA[bi] + (uint32_t)((pr * AROW + pp) * APITCH) * 4u;
            if (((unsigned)gw < (unsigned)W) && ((unsigned)gh < (unsigned)H)) {
                const uint4* src = g_pack + ((size_t)tb * HW + gh * W + gw) * 2;
                cp_async16(dst,       src);
                cp_async16(dst + 16u, src + 1);
            } else {
                uint4 z = make_uint4(0u, 0u, 0u, 0u);
                *(uint4*)((char*)pkd[bi] + (dst - pkdA[bi]))      = z;
                *(uint4*)((char*)pkd[bi] + (dst - pkdA[bi]) + 16) = z;
            }
        }
        asm volatile("cp.async.commit_group;" ::: "memory");
    };

    int t0 = blockIdx.x;
    int p  = 0;
    if (t0 < NTILES) stage_issue(t0, 0);
    __syncthreads();   // weights/bias visible

    for (int t = t0; t < NTILES; t += NCTA) {
        int tn = t + NCTA;
        bool pf = (tn < NTILES);
        if (pf) stage_issue(tn, p ^ 1);
        if (pf) asm volatile("cp.async.wait_group 1;" ::: "memory");
        else    asm volatile("cp.async.wait_group 0;" ::: "memory");
        __syncthreads();

        uint32_t* sIn = pkd[p];
        int b   = t >> 8;
        int rem = t & 255;
        int h0  = (rem >> 1) * 2;
        int w0  = (rem & 1) * 128;

        float acc[2][8][4];
#pragma unroll
        for (int m = 0; m < 2; m++)
#pragma unroll
            for (int j = 0; j < 8; j++)
#pragma unroll
                for (int r = 0; r < 4; r++) acc[m][j][r] = 0.f;

#pragma unroll
        for (int tap = 0; tap < 9; tap++) {
            int arow0 = (wrow + tap / 3) * AROW + (tap % 3);
            uint32_t a[2][4];
#pragma unroll
            for (int m = 0; m < 2; m++) {
                int base0 = (arow0 + pbase + m * 16) * APITCH;
                a[m][0] = sIn[base0 + kc];
                a[m][1] = sIn[base0 + 8 * APITCH + kc];
                a[m][2] = sIn[base0 + kc + 4];
                a[m][3] = sIn[base0 + 8 * APITCH + kc + 4];
            }
            const uint32_t* b0row = sW + (tap * 8 + kc)     * BPITCH + gp;
            const uint32_t* b1row = sW + (tap * 8 + kc + 4) * BPITCH + gp;
#pragma unroll
            for (int j = 0; j < 8; j++) {
                uint32_t b0 = b0row[j * 8];
                uint32_t b1 = b1row[j * 8];
#pragma unroll
                for (int m = 0; m < 2; m++) {
                    asm volatile(
                        "mma.sync.aligned.m16n8k16.row.col.f32.f16.f16.f32 "
                        "{%0,%1,%2,%3}, {%4,%5,%6,%7}, {%8,%9}, {%0,%1,%2,%3};"
                        : "+f"(acc[m][j][0]), "+f"(acc[m][j][1]),
                          "+f"(acc[m][j][2]), "+f"(acc[m][j][3])
                        : "r"(a[m][0]), "r"(a[m][1]), "r"(a[m][2]), "r"(a[m][3]),
                          "r"(b0), "r"(b1));
                }
            }
        }

        // direct stores (8-px runs fill 32B sectors)
        size_t obase = ((size_t)b * OUTC) * HW + (size_t)(h0 + wrow) * W + w0;
#pragma unroll
        for (int m = 0; m < 2; m++) {
            int px = pbase + m * 16;
#pragma unroll
            for (int j = 0; j < 8; j++) {
                int oc0 = j * 8 + 2 * kc;
                float bb0 = sB[oc0], bb1 = sB[oc0 + 1];
                float* o0 = out + obase + (size_t)oc0 * HW + px;
                float* o1 = o0 + HW;
                o0[0] = acc[m][j][0] + bb0;
                o1[0] = acc[m][j][1] + bb1;
                o0[8] = acc[m][j][2] + bb0;
                o1[8] = acc[m][j][3] + bb1;
            }
        }

        // fused copy chunk
        {
            size_t base = (size_t)t * COPY_F4_PER_TILE;
#pragma unroll 4
            for (int i = tid; i < COPY_F4_PER_TILE; i += 256) {
                size_t tt = base + i;
                int ch_slot = (int)(tt >> 14);
                int off     = (int)(tt & 16383);
                int cb = ch_slot / (C - P);
                int j  = ch_slot - cb * (C - P);
                int cc = g_unsel[cb * (C - P) + j];
                const float4* src = (const float4*)(x + ((size_t)(cb * C + cc)) * HW);
                float4* dst = (float4*)(out + (((size_t)cb * OUTC) + OC + j) * HW);
                dst[off] = src[off];
            }
        }
        __syncthreads();   // reads of pkd[p] done before it is restaged
        p ^= 1;
    }
}

// ===========================================================================
extern "C" void kernel_launch(void* const* d_in, const int* in_sizes, int n_in,
                              void* d_out, int out_size) {
    const float* x    = (const float*)d_in[0];
    const float* wgt  = (const float*)d_in[1];
    const float* bias = (const float*)d_in[2];
    float* out = (float*)d_out;

    cudaFuncSetAttribute(k_conv_mma, cudaFuncAttributeMaxDynamicSharedMemorySize,
                         CONV_SMEM);

    k_stats<<<B * C, 512>>>(x);
    k_topk<<<B, 64>>>();
    k_gather<<<B * 128, 256>>>(x);
    k_conv_mma<<<NCTA, 256, CONV_SMEM>>>(x, wgt, bias, out);
}